// round 6
// baseline (speedup 1.0000x reference)
#include <cuda_runtime.h>
#include <cuda_fp16.h>
#include <cstdint>

#define DK 128
#define NB 4096
#define NC 16384
#define TM 128
#define TN 256
#define NTILES 2048            // (NB/TM)*(NC/TN) = 32*64

#define BUF_BYTES 98304        // A 32KB + B 64KB per buffer
#define SMEM_BYTES 196608      // 2 buffers

// Scratch (allocation-free per harness rules)
__device__ __half g_xn[(size_t)NB * DK];
__device__ __half g_pn[(size_t)NC * DK];
__device__ float g_xs[NB];
__device__ float g_ps[NC];

__device__ __forceinline__ uint32_t smem_u32(const void* p) {
    return (uint32_t)__cvta_generic_to_shared(p);
}

// swizzled byte offset for (row, 16B-chunk u in 0..15): conflict-free LDSM + cp.async
__device__ __forceinline__ uint32_t swz(int row, int u) {
    return (uint32_t)(row * 256 + ((u ^ (row & 7)) << 4));
}

__device__ __forceinline__ void cp16(uint32_t dst, const __half* src) {
    asm volatile("cp.async.cg.shared.global [%0], [%1], 16;\n"
                 :: "r"(dst), "l"(__cvta_generic_to_global(src)) : "memory");
}

#define LDSM4(r0, r1, r2, r3, addr)                                          \
    asm volatile("ldmatrix.sync.aligned.m8n8.x4.shared.b16 {%0,%1,%2,%3}, [%4];" \
                 : "=r"(r0), "=r"(r1), "=r"(r2), "=r"(r3) : "r"(addr))

#define MMA16816(d, a, b0, b1)                                               \
    asm volatile("mma.sync.aligned.m16n8k16.row.col.f32.f16.f16.f32 "        \
                 "{%0,%1,%2,%3},{%4,%5,%6,%7},{%8,%9},{%0,%1,%2,%3};"        \
                 : "+f"(d[0]), "+f"(d[1]), "+f"(d[2]), "+f"(d[3])            \
                 : "r"(a[0]), "r"(a[1]), "r"(a[2]), "r"(a[3]), "r"(b0), "r"(b1))

// ---------------- fused normalize: one warp per row over both tensors ----------------
__global__ void normalize_all(const float* __restrict__ inputs,
                              const float* __restrict__ kern) {
    int wid = threadIdx.x >> 5;
    int lane = threadIdx.x & 31;
    int row = blockIdx.x * 8 + wid;
    const float* src;
    __half* dst;
    float* sums;
    int r;
    if (row < NB) { src = inputs; dst = g_xn; sums = g_xs; r = row; }
    else          { src = kern;   dst = g_pn; sums = g_ps; r = row - NB; }
    float4 x = *reinterpret_cast<const float4*>(src + (size_t)r * DK + lane * 4);
    float sq = x.x * x.x + x.y * x.y + x.z * x.z + x.w * x.w;
#pragma unroll
    for (int o = 16; o > 0; o >>= 1) sq += __shfl_xor_sync(0xffffffffu, sq, o);
    float m = fmaxf(sq, 1e-12f);
    float scale = 3.0f * rsqrtf(m);
    __half2 h0 = __floats2half2_rn(x.x * scale, x.y * scale);
    __half2 h1 = __floats2half2_rn(x.z * scale, x.w * scale);
    uint2 st;
    st.x = *reinterpret_cast<uint32_t*>(&h0);
    st.y = *reinterpret_cast<uint32_t*>(&h1);
    *reinterpret_cast<uint2*>(dst + (size_t)r * DK + lane * 4) = st;
    if (lane == 0) sums[r] = 9.0f * (sq / m);
}

// ---------------- persistent double-buffered GEMM + fused epilogue ----------------
#define LOAD_TILE(t_, buf_)                                                       \
    do {                                                                          \
        int bM_ = (t_) & 31, bN_ = (t_) >> 5;                                     \
        const __half* gA_ = g_xn + (size_t)bM_ * TM * DK;                         \
        const __half* gB_ = g_pn + (size_t)bN_ * TN * DK;                         \
        uint32_t ab_ = sbase + (uint32_t)(buf_)*BUF_BYTES;                        \
        uint32_t bb_ = ab_ + 32768;                                               \
        _Pragma("unroll")                                                         \
        for (int j = tid; j < TM * 16; j += 512) {                                \
            int r_ = j >> 4, u_ = j & 15;                                         \
            cp16(ab_ + swz(r_, u_), gA_ + (size_t)r_ * DK + u_ * 8);              \
        }                                                                         \
        _Pragma("unroll")                                                         \
        for (int j = tid; j < TN * 16; j += 512) {                                \
            int r_ = j >> 4, u_ = j & 15;                                         \
            cp16(bb_ + swz(r_, u_), gB_ + (size_t)r_ * DK + u_ * 8);              \
        }                                                                         \
        asm volatile("cp.async.commit_group;\n" ::: "memory");                    \
    } while (0)

__global__ void __launch_bounds__(512, 1) nca_gemm(float* __restrict__ out, int nCTA) {
    extern __shared__ char smem[];
    const int tid = threadIdx.x;
    const int wid = tid >> 5;
    const int lane = tid & 31;
    const int warpM = wid & 1;   // 0..1  (64 rows)
    const int warpN = wid >> 1;  // 0..7  (32 cols)
    const uint32_t sbase = smem_u32(smem);

    const int mseg = lane >> 3;
    const int mrow8 = lane & 7;
    const int a_row_base = warpM * 64 + ((mseg & 1) << 3) + mrow8;
    const int a_u_add = mseg >> 1;
    const int b_row_base = warpN * 32 + ((mseg >> 1) << 3) + mrow8;
    const int b_u_add = mseg & 1;
    const int lg = lane >> 2;
    const int tg = lane & 3;

    if (blockIdx.x < NTILES) LOAD_TILE(blockIdx.x, 0);

    int it = 0;
    for (int t = blockIdx.x; t < NTILES; t += nCTA, ++it) {
        const int pb = it & 1;
        const int nxt = t + nCTA;
        if (nxt < NTILES) {
            LOAD_TILE(nxt, pb ^ 1);
            asm volatile("cp.async.wait_group 1;\n" ::: "memory");
        } else {
            asm volatile("cp.async.wait_group 0;\n" ::: "memory");
        }
        __syncthreads();

        const uint32_t aoff = sbase + (uint32_t)pb * BUF_BYTES;
        const uint32_t boff = aoff + 32768;

        float acc[4][4][4];
#pragma unroll
        for (int mi = 0; mi < 4; mi++)
#pragma unroll
            for (int ni = 0; ni < 4; ni++)
#pragma unroll
                for (int r = 0; r < 4; r++) acc[mi][ni][r] = 0.0f;

#pragma unroll
        for (int ks = 0; ks < 8; ks++) {
            const int ub = ks * 2;
            uint32_t a[4][4], b[2][4];
#pragma unroll
            for (int mi = 0; mi < 4; mi++) {
                LDSM4(a[mi][0], a[mi][1], a[mi][2], a[mi][3],
                      aoff + swz(a_row_base + mi * 16, ub + a_u_add));
            }
#pragma unroll
            for (int nj = 0; nj < 2; nj++) {
                LDSM4(b[nj][0], b[nj][1], b[nj][2], b[nj][3],
                      boff + swz(b_row_base + nj * 16, ub + b_u_add));
            }
#pragma unroll
            for (int mi = 0; mi < 4; mi++) {
#pragma unroll
                for (int ni = 0; ni < 4; ni++) {
                    MMA16816(acc[mi][ni], a[mi], b[ni >> 1][(ni & 1) * 2],
                             b[ni >> 1][(ni & 1) * 2 + 1]);
                }
            }
        }
        __syncthreads();   // all warps done reading buf pb before next prefetch overwrites it

        // epilogue: out = xs + ps - 2*dot
        const int bM = t & 31, bN = t >> 5;
#pragma unroll
        for (int mi = 0; mi < 4; mi++) {
            int r = warpM * 64 + mi * 16 + lg;
            float xs0 = __ldg(g_xs + bM * TM + r);
            float xs1 = __ldg(g_xs + bM * TM + r + 8);
            size_t g0 = (size_t)(bM * TM + r) * NC + bN * TN;
            size_t g1 = g0 + (size_t)8 * NC;
#pragma unroll
            for (int ni = 0; ni < 4; ni++) {
                int c = warpN * 32 + ni * 8 + (tg << 1);
                float p0 = __ldg(g_ps + bN * TN + c);
                float p1 = __ldg(g_ps + bN * TN + c + 1);
                float2 v0, v1;
                v0.x = xs0 + p0 - 2.0f * acc[mi][ni][0];
                v0.y = xs0 + p1 - 2.0f * acc[mi][ni][1];
                v1.x = xs1 + p0 - 2.0f * acc[mi][ni][2];
                v1.y = xs1 + p1 - 2.0f * acc[mi][ni][3];
                *reinterpret_cast<float2*>(out + g0 + c) = v0;
                *reinterpret_cast<float2*>(out + g1 + c) = v1;
            }
        }
    }
}

extern "C" void kernel_launch(void* const* d_in, const int* in_sizes, int n_in,
                              void* d_out, int out_size) {
    const float* inputs = (const float*)d_in[0];   // [4096, 128]
    const float* kern   = (const float*)d_in[1];   // [16384, 128]
    float* out = (float*)d_out;                    // [4096, 16384]

    normalize_all<<<(NB + NC) / 8, 256>>>(inputs, kern);

    int dev = 0, nsm = 148;
    cudaGetDevice(&dev);
    cudaDeviceGetAttribute(&nsm, cudaDevAttrMultiProcessorCount, dev);

    cudaFuncSetAttribute(nca_gemm, cudaFuncAttributeMaxDynamicSharedMemorySize, SMEM_BYTES);
    nca_gemm<<<nsm, 512, SMEM_BYTES>>>(out, nsm);
}

// round 8
// speedup vs baseline: 1.1580x; 1.1580x over previous
#include <cuda_runtime.h>
#include <cuda_fp16.h>
#include <cstdint>

#define DK 128
#define NB 4096
#define NC 16384
#define TM 128
#define TN 128
#define NTILES 4096            // (NB/128)*(NC/128) = 32*128

#define BUF_BYTES 32768        // A chunk 16KB + B chunk 16KB
#define SMEM_BYTES 65536       // 2 buffers

// Scratch (allocation-free per harness rules)
__device__ __half g_xn[(size_t)NB * DK];
__device__ __half g_pn[(size_t)NC * DK];
__device__ float g_xs[NB];
__device__ float g_ps[NC];

__device__ __forceinline__ uint32_t smem_u32(const void* p) {
    return (uint32_t)__cvta_generic_to_shared(p);
}

// 128B rows (K-chunk = 64 fp16), 8 x 16B chunks, XOR swizzle: conflict-free
__device__ __forceinline__ uint32_t swz(int row, int u) {
    return (uint32_t)(row * 128 + ((u ^ (row & 7)) << 4));
}

__device__ __forceinline__ void cp16(uint32_t dst, const __half* src) {
    asm volatile("cp.async.cg.shared.global [%0], [%1], 16;\n"
                 :: "r"(dst), "l"(__cvta_generic_to_global(src)) : "memory");
}

#define LDSM4(r0, r1, r2, r3, addr)                                          \
    asm volatile("ldmatrix.sync.aligned.m8n8.x4.shared.b16 {%0,%1,%2,%3}, [%4];" \
                 : "=r"(r0), "=r"(r1), "=r"(r2), "=r"(r3) : "r"(addr))

#define MMA16816(d, a, b0, b1)                                               \
    asm volatile("mma.sync.aligned.m16n8k16.row.col.f32.f16.f16.f32 "        \
                 "{%0,%1,%2,%3},{%4,%5,%6,%7},{%8,%9},{%0,%1,%2,%3};"        \
                 : "+f"(d[0]), "+f"(d[1]), "+f"(d[2]), "+f"(d[3])            \
                 : "r"(a[0]), "r"(a[1]), "r"(a[2]), "r"(a[3]), "r"(b0), "r"(b1))

// ---------------- fused normalize: one warp per row over both tensors ----------------
__global__ void normalize_all(const float* __restrict__ inputs,
                              const float* __restrict__ kern) {
    int wid = threadIdx.x >> 5;
    int lane = threadIdx.x & 31;
    int row = blockIdx.x * 8 + wid;
    const float* src;
    __half* dst;
    float* sums;
    int r;
    if (row < NB) { src = inputs; dst = g_xn; sums = g_xs; r = row; }
    else          { src = kern;   dst = g_pn; sums = g_ps; r = row - NB; }
    float4 x = *reinterpret_cast<const float4*>(src + (size_t)r * DK + lane * 4);
    float sq = x.x * x.x + x.y * x.y + x.z * x.z + x.w * x.w;
#pragma unroll
    for (int o = 16; o > 0; o >>= 1) sq += __shfl_xor_sync(0xffffffffu, sq, o);
    float m = fmaxf(sq, 1e-12f);
    float scale = 3.0f * rsqrtf(m);
    __half2 h0 = __floats2half2_rn(x.x * scale, x.y * scale);
    __half2 h1 = __floats2half2_rn(x.z * scale, x.w * scale);
    uint2 st;
    st.x = *reinterpret_cast<uint32_t*>(&h0);
    st.y = *reinterpret_cast<uint32_t*>(&h1);
    *reinterpret_cast<uint2*>(dst + (size_t)r * DK + lane * 4) = st;
    if (lane == 0) sums[r] = 9.0f * (sq / m);
}

// Load one 64-wide K chunk of tile t_ into buffer buf_ (A 128x64h + B 128x64h)
#define LOAD_CHUNK(t_, c_, buf_)                                                  \
    do {                                                                          \
        int bM_ = (t_) & 31, bN_ = (t_) >> 5;                                     \
        const __half* gA_ = g_xn + (size_t)bM_ * TM * DK + (c_)*64;               \
        const __half* gB_ = g_pn + (size_t)bN_ * TN * DK + (c_)*64;               \
        uint32_t ab_ = sbase + (uint32_t)(buf_)*BUF_BYTES;                        \
        uint32_t bb_ = ab_ + 16384;                                               \
        _Pragma("unroll")                                                         \
        for (int j = tid; j < TM * 8; j += 256) {                                 \
            int r_ = j >> 3, u_ = j & 7;                                          \
            cp16(ab_ + swz(r_, u_), gA_ + (size_t)r_ * DK + u_ * 8);              \
        }                                                                         \
        _Pragma("unroll")                                                         \
        for (int j = tid; j < TN * 8; j += 256) {                                 \
            int r_ = j >> 3, u_ = j & 7;                                          \
            cp16(bb_ + swz(r_, u_), gB_ + (size_t)r_ * DK + u_ * 8);              \
        }                                                                         \
        asm volatile("cp.async.commit_group;\n" ::: "memory");                    \
    } while (0)

#define COMPUTE_CHUNK(buf_)                                                       \
    do {                                                                          \
        const uint32_t aoff_ = sbase + (uint32_t)(buf_)*BUF_BYTES;                \
        const uint32_t boff_ = aoff_ + 16384;                                     \
        _Pragma("unroll")                                                         \
        for (int ks = 0; ks < 4; ks++) {                                          \
            const int ub = ks * 2;                                                \
            uint32_t a[4][4], b[2][4];                                            \
            _Pragma("unroll")                                                     \
            for (int mi = 0; mi < 4; mi++)                                        \
                LDSM4(a[mi][0], a[mi][1], a[mi][2], a[mi][3],                     \
                      aoff_ + swz(a_row_base + mi * 16, ub + a_u_add));           \
            _Pragma("unroll")                                                     \
            for (int nj = 0; nj < 2; nj++)                                        \
                LDSM4(b[nj][0], b[nj][1], b[nj][2], b[nj][3],                     \
                      boff_ + swz(b_row_base + nj * 16, ub + b_u_add));           \
            _Pragma("unroll")                                                     \
            for (int mi = 0; mi < 4; mi++)                                        \
                _Pragma("unroll")                                                 \
                for (int ni = 0; ni < 4; ni++)                                    \
                    MMA16816(acc[mi][ni], a[mi], b[ni >> 1][(ni & 1) * 2],        \
                             b[ni >> 1][(ni & 1) * 2 + 1]);                       \
        }                                                                         \
    } while (0)

__global__ void __launch_bounds__(256, 2) nca_gemm(float* __restrict__ out, int nCTA) {
    extern __shared__ char smem[];
    const int tid = threadIdx.x;
    const int wid = tid >> 5;
    const int lane = tid & 31;
    const int warpM = wid & 1;   // 0..1  (64 rows)
    const int warpN = wid >> 1;  // 0..3  (32 cols)
    const uint32_t sbase = smem_u32(smem);

    const int mseg = lane >> 3;
    const int mrow8 = lane & 7;
    const int a_row_base = warpM * 64 + ((mseg & 1) << 3) + mrow8;
    const int a_u_add = mseg >> 1;
    const int b_row_base = warpN * 32 + ((mseg >> 1) << 3) + mrow8;
    const int b_u_add = mseg & 1;
    const int lg = lane >> 2;
    const int tg = lane & 3;

    const int t0 = blockIdx.x;
    if (t0 < NTILES) {
        LOAD_CHUNK(t0, 0, 0);   // group
        LOAD_CHUNK(t0, 1, 1);   // group
    }

    for (int t = t0; t < NTILES; t += nCTA) {
        const int nt = t + nCTA;

        float acc[4][4][4];
#pragma unroll
        for (int mi = 0; mi < 4; mi++)
#pragma unroll
            for (int ni = 0; ni < 4; ni++)
#pragma unroll
                for (int r = 0; r < 4; r++) acc[mi][ni][r] = 0.0f;

        // chunk 0 (buf 0); (t,1) stays in flight
        asm volatile("cp.async.wait_group 1;\n" ::: "memory");
        __syncthreads();
        COMPUTE_CHUNK(0);
        __syncthreads();
        if (nt < NTILES) LOAD_CHUNK(nt, 0, 0);

        // chunk 1 (buf 1)
        if (nt < NTILES) {
            asm volatile("cp.async.wait_group 1;\n" ::: "memory");
        } else {
            asm volatile("cp.async.wait_group 0;\n" ::: "memory");
        }
        __syncthreads();
        COMPUTE_CHUNK(1);
        __syncthreads();
        if (nt < NTILES) LOAD_CHUNK(nt, 1, 1);

        // epilogue (overlaps next tile's cp.async DMA): out = xs + ps - 2*dot
        const int bM = t & 31, bN = t >> 5;
#pragma unroll
        for (int mi = 0; mi < 4; mi++) {
            int r = warpM * 64 + mi * 16 + lg;
            float xs0 = __ldg(g_xs + bM * TM + r);
            float xs1 = __ldg(g_xs + bM * TM + r + 8);
            size_t g0 = (size_t)(bM * TM + r) * NC + bN * TN;
            size_t g1 = g0 + (size_t)8 * NC;
#pragma unroll
            for (int ni = 0; ni < 4; ni++) {
                int c = warpN * 32 + ni * 8 + (tg << 1);
                float p0 = __ldg(g_ps + bN * TN + c);
                float p1 = __ldg(g_ps + bN * TN + c + 1);
                float2 v0, v1;
                v0.x = xs0 + p0 - 2.0f * acc[mi][ni][0];
                v0.y = xs0 + p1 - 2.0f * acc[mi][ni][1];
                v1.x = xs1 + p0 - 2.0f * acc[mi][ni][2];
                v1.y = xs1 + p1 - 2.0f * acc[mi][ni][3];
                *reinterpret_cast<float2*>(out + g0 + c) = v0;
                *reinterpret_cast<float2*>(out + g1 + c) = v1;
            }
        }
    }
}

extern "C" void kernel_launch(void* const* d_in, const int* in_sizes, int n_in,
                              void* d_out, int out_size) {
    const float* inputs = (const float*)d_in[0];   // [4096, 128]
    const float* kern   = (const float*)d_in[1];   // [16384, 128]
    float* out = (float*)d_out;                    // [4096, 16384]

    normalize_all<<<(NB + NC) / 8, 256>>>(inputs, kern);

    int dev = 0, nsm = 148;
    cudaGetDevice(&dev);
    cudaDeviceGetAttribute(&nsm, cudaDevAttrMultiProcessorCount, dev);

    cudaFuncSetAttribute(nca_gemm, cudaFuncAttributeMaxDynamicSharedMemorySize, SMEM_BYTES);
    int nCTA = 2 * nsm;
    nca_gemm<<<nCTA, 256, SMEM_BYTES>>>(out, nCTA);
}

// round 9
// speedup vs baseline: 1.2036x; 1.0393x over previous
#include <cuda_runtime.h>
#include <cuda_fp16.h>
#include <cstdint>

#define DK 128
#define NB 4096
#define NC 16384
#define TM 128
#define TN 128
#define NTILES 4096            // 32 * 128

#define BUF_BYTES 32768        // A chunk 16KB + B chunk 16KB
#define SMEM_BYTES 65536       // 2 buffers

// Scratch (allocation-free per harness rules)
__device__ __half g_xn[(size_t)NB * DK];
__device__ __half g_pn[(size_t)NC * DK];
__device__ float g_xs[NB];
__device__ float g_ps[NC];

__device__ __forceinline__ uint32_t smem_u32(const void* p) {
    return (uint32_t)__cvta_generic_to_shared(p);
}

// 128B rows (K-chunk = 64 fp16), 8 x 16B chunks, XOR swizzle: conflict-free
__device__ __forceinline__ uint32_t swz(int row, int u) {
    return (uint32_t)(row * 128 + ((u ^ (row & 7)) << 4));
}

__device__ __forceinline__ void cp16(uint32_t dst, const __half* src) {
    asm volatile("cp.async.cg.shared.global [%0], [%1], 16;\n"
                 :: "r"(dst), "l"(__cvta_generic_to_global(src)) : "memory");
}

#define LDSM4(r0, r1, r2, r3, addr)                                          \
    asm volatile("ldmatrix.sync.aligned.m8n8.x4.shared.b16 {%0,%1,%2,%3}, [%4];" \
                 : "=r"(r0), "=r"(r1), "=r"(r2), "=r"(r3) : "r"(addr))

#define MMA16816(d, a, b0, b1)                                               \
    asm volatile("mma.sync.aligned.m16n8k16.row.col.f32.f16.f16.f32 "        \
                 "{%0,%1,%2,%3},{%4,%5,%6,%7},{%8,%9},{%0,%1,%2,%3};"        \
                 : "+f"(d[0]), "+f"(d[1]), "+f"(d[2]), "+f"(d[3])            \
                 : "r"(a[0]), "r"(a[1]), "r"(a[2]), "r"(a[3]), "r"(b0), "r"(b1))

// ---------------- fused normalize: one warp per row over both tensors ----------------
__global__ void normalize_all(const float* __restrict__ inputs,
                              const float* __restrict__ kern) {
    int wid = threadIdx.x >> 5;
    int lane = threadIdx.x & 31;
    int row = blockIdx.x * 8 + wid;
    const float* src;
    __half* dst;
    float* sums;
    int r;
    if (row < NB) { src = inputs; dst = g_xn; sums = g_xs; r = row; }
    else          { src = kern;   dst = g_pn; sums = g_ps; r = row - NB; }
    float4 x = *reinterpret_cast<const float4*>(src + (size_t)r * DK + lane * 4);
    float sq = x.x * x.x + x.y * x.y + x.z * x.z + x.w * x.w;
#pragma unroll
    for (int o = 16; o > 0; o >>= 1) sq += __shfl_xor_sync(0xffffffffu, sq, o);
    float m = fmaxf(sq, 1e-12f);
    float scale = 3.0f * rsqrtf(m);
    __half2 h0 = __floats2half2_rn(x.x * scale, x.y * scale);
    __half2 h1 = __floats2half2_rn(x.z * scale, x.w * scale);
    uint2 st;
    st.x = *reinterpret_cast<uint32_t*>(&h0);
    st.y = *reinterpret_cast<uint32_t*>(&h1);
    *reinterpret_cast<uint2*>(dst + (size_t)r * DK + lane * 4) = st;
    if (lane == 0) sums[r] = 9.0f * (sq / m);
}

// Load one 64-wide K chunk of tile t_ into buffer buf_ (A 128x64h + B 128x64h)
#define LOAD_CHUNK(t_, c_, buf_)                                                  \
    do {                                                                          \
        int bM_ = (t_) & 31, bN_ = (t_) >> 5;                                     \
        const __half* gA_ = g_xn + (size_t)bM_ * TM * DK + (c_)*64;               \
        const __half* gB_ = g_pn + (size_t)bN_ * TN * DK + (c_)*64;               \
        uint32_t ab_ = sbase + (uint32_t)(buf_)*BUF_BYTES;                        \
        uint32_t bb_ = ab_ + 16384;                                               \
        _Pragma("unroll")                                                         \
        for (int j = tid; j < TM * 8; j += 128) {                                 \
            int r_ = j >> 3, u_ = j & 7;                                          \
            cp16(ab_ + swz(r_, u_), gA_ + (size_t)r_ * DK + u_ * 8);              \
        }                                                                         \
        _Pragma("unroll")                                                         \
        for (int j = tid; j < TN * 8; j += 128) {                                 \
            int r_ = j >> 3, u_ = j & 7;                                          \
            cp16(bb_ + swz(r_, u_), gB_ + (size_t)r_ * DK + u_ * 8);              \
        }                                                                         \
        asm volatile("cp.async.commit_group;\n" ::: "memory");                    \
    } while (0)

#define COMPUTE_CHUNK(buf_)                                                       \
    do {                                                                          \
        const uint32_t aoff_ = sbase + (uint32_t)(buf_)*BUF_BYTES;                \
        const uint32_t boff_ = aoff_ + 16384;                                     \
        _Pragma("unroll")                                                         \
        for (int ks = 0; ks < 4; ks++) {                                          \
            const int ub = ks * 2;                                                \
            uint32_t a[4][4], b[4][4];                                            \
            _Pragma("unroll")                                                     \
            for (int mi = 0; mi < 4; mi++)                                        \
                LDSM4(a[mi][0], a[mi][1], a[mi][2], a[mi][3],                     \
                      aoff_ + swz(a_row_base + mi * 16, ub + a_u_add));           \
            _Pragma("unroll")                                                     \
            for (int nj = 0; nj < 4; nj++)                                        \
                LDSM4(b[nj][0], b[nj][1], b[nj][2], b[nj][3],                     \
                      boff_ + swz(b_row_base + nj * 16, ub + b_u_add));           \
            _Pragma("unroll")                                                     \
            for (int mi = 0; mi < 4; mi++)                                        \
                _Pragma("unroll")                                                 \
                for (int ni = 0; ni < 8; ni++)                                    \
                    MMA16816(acc[mi][ni], a[mi], b[ni >> 1][(ni & 1) * 2],        \
                             b[ni >> 1][(ni & 1) * 2 + 1]);                       \
        }                                                                         \
    } while (0)

__global__ void __launch_bounds__(128, 2) nca_gemm(float* __restrict__ out, int nCTA) {
    extern __shared__ char smem[];
    const int tid = threadIdx.x;
    const int wid = tid >> 5;
    const int lane = tid & 31;
    const int warpM = wid & 1;   // 0..1  (64 rows)
    const int warpN = wid >> 1;  // 0..1  (64 cols)
    const uint32_t sbase = smem_u32(smem);

    const int mseg = lane >> 3;
    const int mrow8 = lane & 7;
    const int a_row_base = warpM * 64 + ((mseg & 1) << 3) + mrow8;
    const int a_u_add = mseg >> 1;
    const int b_row_base = warpN * 64 + ((mseg >> 1) << 3) + mrow8;
    const int b_u_add = mseg & 1;
    const int lg = lane >> 2;
    const int tg = lane & 3;
    const int todd = tg & 1;

    const int t0 = blockIdx.x;
    if (t0 < NTILES) {
        LOAD_CHUNK(t0, 0, 0);
        LOAD_CHUNK(t0, 1, 1);
    }

    for (int t = t0; t < NTILES; t += nCTA) {
        const int nt = t + nCTA;

        float acc[4][8][4];
#pragma unroll
        for (int mi = 0; mi < 4; mi++)
#pragma unroll
            for (int ni = 0; ni < 8; ni++)
#pragma unroll
                for (int r = 0; r < 4; r++) acc[mi][ni][r] = 0.0f;

        asm volatile("cp.async.wait_group 1;\n" ::: "memory");
        __syncthreads();
        COMPUTE_CHUNK(0);
        __syncthreads();
        if (nt < NTILES) LOAD_CHUNK(nt, 0, 0);

        if (nt < NTILES) {
            asm volatile("cp.async.wait_group 1;\n" ::: "memory");
        } else {
            asm volatile("cp.async.wait_group 0;\n" ::: "memory");
        }
        __syncthreads();
        COMPUTE_CHUNK(1);
        __syncthreads();
        if (nt < NTILES) LOAD_CHUNK(nt, 1, 1);

        // Epilogue: out = xs + ps - 2*dot, STG.128 via lane-pair exchange.
        // even tg: row lg, cols c..c+3; odd tg: row lg+8, cols c..c+3 (c = ni*8 + (tg&2)*2)
        const int bM = t & 31, bN = t >> 5;
#pragma unroll
        for (int mi = 0; mi < 4; mi++) {
            int rbase = warpM * 64 + mi * 16 + lg;
            int r = rbase + (todd ? 8 : 0);
            float xs = __ldg(g_xs + bM * TM + r);
            size_t grow = (size_t)(bM * TM + r) * NC + bN * TN;
#pragma unroll
            for (int ni = 0; ni < 8; ni++) {
                float v0 = acc[mi][ni][0], v1 = acc[mi][ni][1];
                float v2 = acc[mi][ni][2], v3 = acc[mi][ni][3];
                float s0 = __shfl_xor_sync(0xffffffffu, todd ? v0 : v2, 1);
                float s1 = __shfl_xor_sync(0xffffffffu, todd ? v1 : v3, 1);
                float w0 = todd ? s0 : v0;
                float w1 = todd ? s1 : v1;
                float w2 = todd ? v2 : s0;
                float w3 = todd ? v3 : s1;
                int c = warpN * 64 + ni * 8 + (tg & 2) * 2;
                float4 pv = __ldg(reinterpret_cast<const float4*>(g_ps + bN * TN + c));
                float4 o;
                o.x = xs + pv.x - 2.0f * w0;
                o.y = xs + pv.y - 2.0f * w1;
                o.z = xs + pv.z - 2.0f * w2;
                o.w = xs + pv.w - 2.0f * w3;
                *reinterpret_cast<float4*>(out + grow + c) = o;
            }
        }
    }
}

extern "C" void kernel_launch(void* const* d_in, const int* in_sizes, int n_in,
                              void* d_out, int out_size) {
    const float* inputs = (const float*)d_in[0];   // [4096, 128]
    const float* kern   = (const float*)d_in[1];   // [16384, 128]
    float* out = (float*)d_out;                    // [4096, 16384]

    normalize_all<<<(NB + NC) / 8, 256>>>(inputs, kern);

    int dev = 0, nsm = 148;
    cudaGetDevice(&dev);
    cudaDeviceGetAttribute(&nsm, cudaDevAttrMultiProcessorCount, dev);

    cudaFuncSetAttribute(nca_gemm, cudaFuncAttributeMaxDynamicSharedMemorySize, SMEM_BYTES);
    int nCTA = 2 * nsm;
    nca_gemm<<<nCTA, 128, SMEM_BYTES>>>(out, nCTA);
}